// round 8
// baseline (speedup 1.0000x reference)
#include <cuda_runtime.h>
#include <math.h>
#include <stdint.h>

#define TT 512
#define CC 128
#define HH 512
#define ROWS 1024
#define PA 129            // dup-A pitch in ull (odd -> conflict-free rows)

// ---------------- globals (cross-kernel intermediates) ----------------
__device__ float g_v[ROWS*CC];
__device__ float g_k[ROWS*CC];
__device__ float g_r[ROWS*CC];

// ---------------- helpers ----------------
__device__ __forceinline__ float wsum(float x) {
    #pragma unroll
    for (int o = 16; o; o >>= 1) x += __shfl_xor_sync(0xffffffffu, x, o);
    return x;
}
__device__ __forceinline__ float rcpa(float x) {
    float r; asm("rcp.approx.f32 %0, %1;" : "=f"(r) : "f"(x)); return r;
}
typedef unsigned long long ull;
__device__ __forceinline__ ull pack2(float x, float y) {
    ull r; asm("mov.b64 %0, {%1, %2};" : "=l"(r) : "f"(x), "f"(y)); return r;
}
__device__ __forceinline__ void unpack2(ull p, float& x, float& y) {
    asm("mov.b64 {%0, %1}, %2;" : "=f"(x), "=f"(y) : "l"(p));
}
__device__ __forceinline__ ull fma2(ull a, ull b, ull c) {
    ull d; asm("fma.rn.f32x2 %0, %1, %2, %3;" : "=l"(d) : "l"(a), "l"(b), "l"(c)); return d;
}
__device__ __forceinline__ ull mul2(ull a, ull b) {
    ull d; asm("mul.rn.f32x2 %0, %1, %2;" : "=l"(d) : "l"(a), "l"(b)); return d;
}
__device__ __forceinline__ ull add2(ull a, ull b) {
    ull d; asm("add.rn.f32x2 %0, %1, %2;" : "=l"(d) : "l"(a), "l"(b)); return d;
}

// ---------------- GEMM: 8 rows x 128 cols, barrier-free mainloop ----------------
// Warp w owns cols [16w,16w+16); lane: colpair c2 = 16w + (lane&7)*2,
// rowpair r0 = 2*(lane>>3). A: dup f32x2 in smem [8][PA]; B: global (L2).
// acc0 += A[r0][k]*(B[k][c2],B[k][c2+1]); acc1 same for r0+1. Accumulating.
__device__ __forceinline__ void gemm128(const ull* __restrict__ Ad,
                                        const float* __restrict__ W, int ldw, int bn,
                                        ull& acc0, ull& acc1) {
    const int tid = threadIdx.x, w = tid >> 5, lane = tid & 31;
    const int c2 = bn + (w << 4) + ((lane & 7) << 1);
    const int r0 = (lane >> 3) << 1;
    const ull* a0p = Ad + r0*PA;
    const ull* a1p = a0p + PA;
    const float* Wp = W + c2;
    #pragma unroll 8
    for (int k = 0; k < CC; k++) {
        ull b = *(const ull*)(Wp + (size_t)k*ldw);
        acc0 = fma2(a0p[k], b, acc0);
        acc1 = fma2(a1p[k], b, acc1);
    }
}

// scatter accs to Red[8][132] (float) so epilogue threads can read (row=warp, 4 cols)
__device__ __forceinline__ void acc_to_red(float* __restrict__ Red, ull acc0, ull acc1) {
    const int tid = threadIdx.x, w = tid >> 5, lane = tid & 31;
    const int c  = (w << 4) + ((lane & 7) << 1);
    const int r0 = (lane >> 3) << 1;
    float x0, x1, y0, y1;
    unpack2(acc0, x0, x1); unpack2(acc1, y0, y1);
    Red[r0*132 + c] = x0;       Red[r0*132 + c + 1] = x1;
    Red[(r0+1)*132 + c] = y0;   Red[(r0+1)*132 + c + 1] = y1;
}

// ================= Kernel A: LN1 + shift + v/r/k GEMMs =================
struct __align__(16) SmemA {
    ull   hs[8*PA];          // 8256 (dup A)
    float lnaux[10][CC];     // 5120
    float Red[8*132];        // 4224
};

__global__ void __launch_bounds__(256, 1)
kernelA(const float* __restrict__ x,
        const float* __restrict__ ln1_g, const float* __restrict__ ln1_b,
        const float* __restrict__ mu,
        const float* __restrict__ Wr, const float* __restrict__ br,
        const float* __restrict__ Wk, const float* __restrict__ bk,
        const float* __restrict__ Wv, const float* __restrict__ bv) {
    __shared__ SmemA S;
    const int tid = threadIdx.x, w = tid >> 5, lane = tid & 31;
    const int bid = blockIdx.x;
    const int bb = bid >> 6;
    const int t0 = (bid & 63) << 3;
    const int bm = bid << 3;

    // LN1 + temporal shift (8 rows + halo), write dup-A
    {
        float4 g4 = *(const float4*)(ln1_g + (lane << 2));
        float4 b4 = *(const float4*)(ln1_b + (lane << 2));
        for (int hr = w; hr < 10; hr += 8) {
            int t = t0 - 1 + hr;
            bool ok = (t >= 0) && (t < TT);
            float4 xv = make_float4(0.f, 0.f, 0.f, 0.f);
            if (ok) xv = *(const float4*)(x + (size_t)((bb << 9) + t)*CC + (lane << 2));
            float mean = wsum((xv.x + xv.y) + (xv.z + xv.w)) * (1.0f/CC);
            float d0 = xv.x - mean, d1 = xv.y - mean, d2 = xv.z - mean, d3 = xv.w - mean;
            float rs = rsqrtf(wsum((d0*d0 + d1*d1) + (d2*d2 + d3*d3)) * (1.0f/CC) + 1e-5f);
            int c = lane << 2;
            S.lnaux[hr][c+0] = ok ? d0*rs*g4.x + b4.x : 0.f;
            S.lnaux[hr][c+1] = ok ? d1*rs*g4.y + b4.y : 0.f;
            S.lnaux[hr][c+2] = ok ? d2*rs*g4.z + b4.z : 0.f;
            S.lnaux[hr][c+3] = ok ? d3*rs*g4.w + b4.w : 0.f;
        }
        __syncthreads();
        for (int i = tid; i < 8*CC; i += 256) {
            int rl = i >> 7, c = i & (CC-1);
            float val = S.lnaux[rl+1][c];
            float shv = (c < CC/2) ? S.lnaux[rl][c] : S.lnaux[rl+2][c];
            float hsv = val + mu[c]*shv;
            S.hs[rl*PA + c] = pack2(hsv, hsv);
        }
        __syncthreads();
    }

    // ---- V ----
    {
        ull a0 = 0ull, a1 = 0ull;
        gemm128(S.hs, Wv, CC, 0, a0, a1);
        acc_to_red(S.Red, a0, a1);
        __syncthreads();
        float4 s = *(float4*)&S.Red[w*132 + (lane << 2)];
        float4 b4 = *(const float4*)(bv + (lane << 2));
        *(float4*)(g_v + (size_t)(bm + w)*CC + (lane << 2)) =
            make_float4(s.x+b4.x, s.y+b4.y, s.z+b4.z, s.w+b4.w);
        __syncthreads();
    }
    // ---- R (sigmoid) ----
    {
        ull a0 = 0ull, a1 = 0ull;
        gemm128(S.hs, Wr, CC, 0, a0, a1);
        acc_to_red(S.Red, a0, a1);
        __syncthreads();
        float4 s = *(float4*)&S.Red[w*132 + (lane << 2)];
        float4 b4 = *(const float4*)(br + (lane << 2));
        float v0 = s.x+b4.x, v1 = s.y+b4.y, v2 = s.z+b4.z, v3 = s.w+b4.w;
        *(float4*)(g_r + (size_t)(bm + w)*CC + (lane << 2)) =
            make_float4(1.0f/(1.0f+expf(-v0)), 1.0f/(1.0f+expf(-v1)),
                        1.0f/(1.0f+expf(-v2)), 1.0f/(1.0f+expf(-v3)));
        __syncthreads();
    }
    // ---- K ----
    {
        ull a0 = 0ull, a1 = 0ull;
        gemm128(S.hs, Wk, CC, 0, a0, a1);
        acc_to_red(S.Red, a0, a1);
        __syncthreads();
        float4 s = *(float4*)&S.Red[w*132 + (lane << 2)];
        float4 b4 = *(const float4*)(bk + (lane << 2));
        *(float4*)(g_k + (size_t)(bm + w)*CC + (lane << 2)) =
            make_float4(s.x+b4.x, s.y+b4.y, s.z+b4.z, s.w+b4.w);
    }
}

// ================= Kernel B: WKV + Wo/LN2 + MLP =================
struct __align__(16) SmemB {
    ull   h2s [8*PA];        // 8256  (also mid tile 3)
    ull   wks [8*PA];        // 8256  (also mid tile 2)
    ull   midB[2][8*PA];     // 16512 (mid tiles 0,1)
    float ys  [8*CC];        // 4096
    float Red [8*132];       // 4224
};                           // 41344 bytes static

__global__ void __launch_bounds__(256, 1)
kernelB(const float* __restrict__ x,
        const float* __restrict__ wd,
        const float* __restrict__ Wo, const float* __restrict__ bo,
        const float* __restrict__ g2, const float* __restrict__ be2,
        const float* __restrict__ W1, const float* __restrict__ b1,
        const float* __restrict__ W2, const float* __restrict__ b2,
        float* __restrict__ out) {
    __shared__ SmemB S;
    const int tid = threadIdx.x, w = tid >> 5, lane = tid & 31;
    const int bid = blockIdx.x;
    const int bb = bid >> 6;
    const int bm = bid << 3;
    const int row = bm + w;

    // ---- WKV: warp = row; 2 independent l-chains, even/odd across lane halves.
    // x_b == x_f identity -> wk = r * x_f. Result -> wks (dup pairs).
    {
        const int h = lane >> 4, p = lane & 15, c0 = p << 3;
        float bv8[8], rrow[8];
        {
            float4 k0 = *(const float4*)(g_k + (size_t)row*CC + c0);
            float4 k1 = *(const float4*)(g_k + (size_t)row*CC + c0 + 4);
            float4 w0 = *(const float4*)(wd + c0);
            float4 w1 = *(const float4*)(wd + c0 + 4);
            bv8[0] = k0.x * (-expf(w0.x)); bv8[1] = k0.y * (-expf(w0.y));
            bv8[2] = k0.z * (-expf(w0.z)); bv8[3] = k0.w * (-expf(w0.w));
            bv8[4] = k1.x * (-expf(w1.x)); bv8[5] = k1.y * (-expf(w1.y));
            bv8[6] = k1.z * (-expf(w1.z)); bv8[7] = k1.w * (-expf(w1.w));
            float4 r0 = *(const float4*)(g_r + (size_t)row*CC + c0);
            float4 r1 = *(const float4*)(g_r + (size_t)row*CC + c0 + 4);
            rrow[0]=r0.x; rrow[1]=r0.y; rrow[2]=r0.z; rrow[3]=r0.w;
            rrow[4]=r1.x; rrow[5]=r1.y; rrow[6]=r1.z; rrow[7]=r1.w;
        }
        float amax = bv8[0];
        #pragma unroll
        for (int i = 1; i < 8; i++) amax = fmaxf(amax, bv8[i]);
        #pragma unroll
        for (int o = 16; o; o >>= 1) amax = fmaxf(amax, __shfl_xor_sync(0xffffffffu, amax, o));
        #pragma unroll
        for (int i = 0; i < 8; i++) bv8[i] -= amax;

        const float inv511 = 1.0f/511.0f;
        const float sA = (float)(511 - h) * inv511;
        const float sB = (float)(255 - h) * inv511;
        ull Ea[4], Eb[4], gstep[4];
        #pragma unroll
        for (int j = 0; j < 4; j++) {
            Ea[j]    = pack2(expf(bv8[2*j]*sA),           expf(bv8[2*j+1]*sA));
            Eb[j]    = pack2(expf(bv8[2*j]*sB),           expf(bv8[2*j+1]*sB));
            gstep[j] = pack2(expf(-2.0f*bv8[2*j]*inv511), expf(-2.0f*bv8[2*j+1]*inv511));
        }
        ull acc2[4] = {0ull, 0ull, 0ull, 0ull};
        const float* vpA = g_v + ((size_t)(bb << 9) + h)*CC + c0;
        const float* vpB = vpA + 256*CC;

        #pragma unroll 2
        for (int i = 0; i < 128; i++) {
            ull ta = add2(add2(Ea[0], Ea[1]), add2(Ea[2], Ea[3]));
            ull tb = add2(add2(Eb[0], Eb[1]), add2(Eb[2], Eb[3]));
            float al, ah, bl, bh;
            unpack2(ta, al, ah); unpack2(tb, bl, bh);
            float za = al + ah, zb = bl + bh;
            #pragma unroll
            for (int o = 8; o; o >>= 1) {
                za += __shfl_xor_sync(0xffffffffu, za, o);
                zb += __shfl_xor_sync(0xffffffffu, zb, o);
            }
            float ia = rcpa(za + 1e-6f), ib = rcpa(zb + 1e-6f);
            ull invA = pack2(ia, ia), invB = pack2(ib, ib);
            ulonglong2 vA01 = *(const ulonglong2*)(vpA);
            ulonglong2 vA23 = *(const ulonglong2*)(vpA + 4);
            ulonglong2 vB01 = *(const ulonglong2*)(vpB);
            ulonglong2 vB23 = *(const ulonglong2*)(vpB + 4);
            acc2[0] = fma2(mul2(Ea[0], invA), vA01.x, acc2[0]);
            acc2[1] = fma2(mul2(Ea[1], invA), vA01.y, acc2[1]);
            acc2[2] = fma2(mul2(Ea[2], invA), vA23.x, acc2[2]);
            acc2[3] = fma2(mul2(Ea[3], invA), vA23.y, acc2[3]);
            acc2[0] = fma2(mul2(Eb[0], invB), vB01.x, acc2[0]);
            acc2[1] = fma2(mul2(Eb[1], invB), vB01.y, acc2[1]);
            acc2[2] = fma2(mul2(Eb[2], invB), vB23.x, acc2[2]);
            acc2[3] = fma2(mul2(Eb[3], invB), vB23.y, acc2[3]);
            Ea[0] = mul2(Ea[0], gstep[0]); Ea[1] = mul2(Ea[1], gstep[1]);
            Ea[2] = mul2(Ea[2], gstep[2]); Ea[3] = mul2(Ea[3], gstep[3]);
            Eb[0] = mul2(Eb[0], gstep[0]); Eb[1] = mul2(Eb[1], gstep[1]);
            Eb[2] = mul2(Eb[2], gstep[2]); Eb[3] = mul2(Eb[3], gstep[3]);
            vpA += 2*CC; vpB += 2*CC;
        }
        #pragma unroll
        for (int j = 0; j < 4; j++) {
            float xx, yy; unpack2(acc2[j], xx, yy);
            xx += __shfl_xor_sync(0xffffffffu, xx, 16);
            yy += __shfl_xor_sync(0xffffffffu, yy, 16);
            if (h == 0) {
                float q0 = rrow[2*j]   * xx;
                float q1 = rrow[2*j+1] * yy;
                S.wks[w*PA + c0 + 2*j    ] = pack2(q0, q0);
                S.wks[w*PA + c0 + 2*j + 1] = pack2(q1, q1);
            }
        }
    }
    __syncthreads();

    // ---- Wo + residual + LN2 -> h2s (dup) ----
    {
        ull a0 = 0ull, a1 = 0ull;
        gemm128(S.wks, Wo, CC, 0, a0, a1);
        acc_to_red(S.Red, a0, a1);
        __syncthreads();
        float4 s   = *(float4*)&S.Red[w*132 + (lane << 2)];
        float4 b4v = *(const float4*)(bo  + (lane << 2));
        float4 g4  = *(const float4*)(g2  + (lane << 2));
        float4 b4  = *(const float4*)(be2 + (lane << 2));
        float4 xv  = *(const float4*)(x + (size_t)row*CC + (lane << 2));
        float y0 = s.x + b4v.x + xv.x;
        float y1 = s.y + b4v.y + xv.y;
        float y2 = s.z + b4v.z + xv.z;
        float y3 = s.w + b4v.w + xv.w;
        *(float4*)&S.ys[w*CC + (lane << 2)] = make_float4(y0, y1, y2, y3);
        float mean = wsum((y0 + y1) + (y2 + y3)) * (1.0f/CC);
        float d0 = y0 - mean, d1 = y1 - mean, d2 = y2 - mean, d3 = y3 - mean;
        float rs = rsqrtf(wsum((d0*d0 + d1*d1) + (d2*d2 + d3*d3)) * (1.0f/CC) + 1e-5f);
        float h0 = d0*rs*g4.x + b4.x, h1 = d1*rs*g4.y + b4.y;
        float h2v = d2*rs*g4.z + b4.z, h3 = d3*rs*g4.w + b4.w;
        int c = lane << 2;
        S.h2s[w*PA + c+0] = pack2(h0, h0);
        S.h2s[w*PA + c+1] = pack2(h1, h1);
        S.h2s[w*PA + c+2] = pack2(h2v, h2v);
        S.h2s[w*PA + c+3] = pack2(h3, h3);
        __syncthreads();
    }

    // ---- W1 + exact gelu -> mid tiles {midB0, midB1, wks, h2s} (dup) ----
    #pragma unroll 1
    for (int nb = 0; nb < 4; nb++) {
        ull a0 = 0ull, a1 = 0ull;
        gemm128(S.h2s, W1, HH, nb << 7, a0, a1);
        acc_to_red(S.Red, a0, a1);
        __syncthreads();
        ull* tgt = (nb == 0) ? S.midB[0] : (nb == 1) ? S.midB[1]
                 : (nb == 2) ? S.wks : S.h2s;
        float4 s   = *(float4*)&S.Red[w*132 + (lane << 2)];
        float4 b4v = *(const float4*)(b1 + (nb << 7) + (lane << 2));
        float v0 = s.x+b4v.x, v1 = s.y+b4v.y, v2 = s.z+b4v.z, v3 = s.w+b4v.w;
        const float gc = 0.70710678118654752f;
        v0 = 0.5f*v0*(1.0f + erff(v0*gc));
        v1 = 0.5f*v1*(1.0f + erff(v1*gc));
        v2 = 0.5f*v2*(1.0f + erff(v2*gc));
        v3 = 0.5f*v3*(1.0f + erff(v3*gc));
        int c = lane << 2;
        tgt[w*PA + c+0] = pack2(v0, v0);
        tgt[w*PA + c+1] = pack2(v1, v1);
        tgt[w*PA + c+2] = pack2(v2, v2);
        tgt[w*PA + c+3] = pack2(v3, v3);
        __syncthreads();
    }

    // ---- W2 (K=512 via 4 segments) + residual -> out ----
    {
        ull a0 = 0ull, a1 = 0ull;
        gemm128(S.midB[0], W2,            CC, 0, a0, a1);
        gemm128(S.midB[1], W2 + 128*CC,   CC, 0, a0, a1);
        gemm128(S.wks,     W2 + 256*CC,   CC, 0, a0, a1);
        gemm128(S.h2s,     W2 + 384*CC,   CC, 0, a0, a1);
        acc_to_red(S.Red, a0, a1);
        __syncthreads();
        float4 s   = *(float4*)&S.Red[w*132 + (lane << 2)];
        float4 b4v = *(const float4*)(b2 + (lane << 2));
        float4 yv  = *(float4*)&S.ys[w*CC + (lane << 2)];
        *(float4*)(out + (size_t)row*CC + (lane << 2)) =
            make_float4(s.x + b4v.x + yv.x, s.y + b4v.y + yv.y,
                        s.z + b4v.z + yv.z, s.w + b4v.w + yv.w);
    }
}

// ---------------- launch ----------------
extern "C" void kernel_launch(void* const* d_in, const int* in_sizes, int n_in,
                              void* d_out, int out_size) {
    const float* x       = (const float*)d_in[0];
    const float* ln1_g   = (const float*)d_in[1];
    const float* ln1_b   = (const float*)d_in[2];
    const float* mu      = (const float*)d_in[3];
    const float* Wr      = (const float*)d_in[4];
    const float* br      = (const float*)d_in[5];
    const float* Wk      = (const float*)d_in[6];
    const float* bk      = (const float*)d_in[7];
    const float* Wv      = (const float*)d_in[8];
    const float* bv      = (const float*)d_in[9];
    const float* w_decay = (const float*)d_in[10];
    const float* Wo      = (const float*)d_in[11];
    const float* bo      = (const float*)d_in[12];
    const float* ln2_g   = (const float*)d_in[13];
    const float* ln2_b   = (const float*)d_in[14];
    const float* W1      = (const float*)d_in[15];
    const float* b1      = (const float*)d_in[16];
    const float* W2      = (const float*)d_in[17];
    const float* b2      = (const float*)d_in[18];
    float* out = (float*)d_out;

    kernelA<<<128, 256>>>(x, ln1_g, ln1_b, mu, Wr, br, Wk, bk, Wv, bv);
    kernelB<<<128, 256>>>(x, w_decay, Wo, bo, ln2_g, ln2_b, W1, b1, W2, b2, out);
}

// round 9
// speedup vs baseline: 1.1847x; 1.1847x over previous
#include <cuda_runtime.h>
#include <math.h>
#include <stdint.h>

#define TT 512
#define CC 128
#define HH 512
#define ROWS 1024
#define CH 16

// ---------------- scratch ----------------
__device__ float g_hs [ROWS*CC];
__device__ float g_r  [ROWS*CC];
__device__ float g_k  [ROWS*CC];
__device__ float g_v  [ROWS*CC];
__device__ float g_wk [ROWS*CC];
__device__ float g_y  [ROWS*CC];
__device__ float g_h2 [ROWS*CC];
__device__ float g_mid[ROWS*HH];

// ---------------- helpers ----------------
__device__ __forceinline__ float wsum(float x) {
    #pragma unroll
    for (int o = 16; o; o >>= 1) x += __shfl_xor_sync(0xffffffffu, x, o);
    return x;
}
__device__ __forceinline__ float rcpa(float x) {
    float r; asm("rcp.approx.f32 %0, %1;" : "=f"(r) : "f"(x)); return r;
}
typedef unsigned long long ull;
__device__ __forceinline__ ull pack2(float x, float y) {
    ull r; asm("mov.b64 %0, {%1, %2};" : "=l"(r) : "f"(x), "f"(y)); return r;
}
__device__ __forceinline__ void unpack2(ull p, float& x, float& y) {
    asm("mov.b64 {%0, %1}, %2;" : "=f"(x), "=f"(y) : "l"(p));
}
__device__ __forceinline__ ull fma2(ull a, ull b, ull c) {
    ull d; asm("fma.rn.f32x2 %0, %1, %2, %3;" : "=l"(d) : "l"(a), "l"(b), "l"(c)); return d;
}
__device__ __forceinline__ ull mul2(ull a, ull b) {
    ull d; asm("mul.rn.f32x2 %0, %1, %2;" : "=l"(d) : "l"(a), "l"(b)); return d;
}
__device__ __forceinline__ ull add2(ull a, ull b) {
    ull d; asm("add.rn.f32x2 %0, %1, %2;" : "=l"(d) : "l"(a), "l"(b)); return d;
}
__device__ __forceinline__ void cpasync16(uint32_t saddr, const void* g) {
    asm volatile("cp.async.ca.shared.global [%0], [%1], 16;" :: "r"(saddr), "l"(g));
}
__device__ __forceinline__ void cpcommit() { asm volatile("cp.async.commit_group;"); }
template<int N> __device__ __forceinline__ void cpwait() {
    asm volatile("cp.async.wait_group %0;" :: "n"(N));
}

// ---------------- fused LN1 + TemporalShift (round-5, proven) ----------------
__global__ void __launch_bounds__(256)
ln_shift_kernel(const float* __restrict__ x,
                const float* __restrict__ gam, const float* __restrict__ bet,
                const float* __restrict__ mu, float* __restrict__ hs) {
    __shared__ float sh[10][CC];
    const int tid = threadIdx.x;
    const int w = tid >> 5, lane = tid & 31;
    const int b  = blockIdx.x >> 6;
    const int t0 = (blockIdx.x & 63) << 3;

    float4 g4 = *(const float4*)(gam + (lane << 2));
    float4 b4 = *(const float4*)(bet + (lane << 2));

    for (int hr = w; hr < 10; hr += 8) {
        int t = t0 - 1 + hr;
        bool ok = (t >= 0) && (t < TT);
        float4 xv = make_float4(0.f, 0.f, 0.f, 0.f);
        if (ok) xv = *(const float4*)(x + (size_t)((b << 9) + t)*CC + (lane << 2));
        float mean = wsum((xv.x + xv.y) + (xv.z + xv.w)) * (1.0f/CC);
        float d0 = xv.x - mean, d1 = xv.y - mean, d2 = xv.z - mean, d3 = xv.w - mean;
        float rs = rsqrtf(wsum((d0*d0 + d1*d1) + (d2*d2 + d3*d3)) * (1.0f/CC) + 1e-5f);
        int c = lane << 2;
        sh[hr][c+0] = ok ? d0*rs*g4.x + b4.x : 0.f;
        sh[hr][c+1] = ok ? d1*rs*g4.y + b4.y : 0.f;
        sh[hr][c+2] = ok ? d2*rs*g4.z + b4.z : 0.f;
        sh[hr][c+3] = ok ? d3*rs*g4.w + b4.w : 0.f;
    }
    __syncthreads();
    for (int i = tid; i < 8*CC; i += 256) {
        int rl = i >> 7, c = i & (CC-1);
        float val = sh[rl+1][c];
        float shv = (c < CC/2) ? sh[rl][c] : sh[rl+2][c];
        hs[(size_t)((b << 9) + t0 + rl)*CC + c] = val + mu[c]*shv;
    }
}

// ---------------- GEMM64: 8 rows x 64 cols, 128 thr, 4-way split-K ----------------
struct __align__(16) SmemG {
    float Bs[2][CH][64];    // 8 KB (aliased as Red ull[4][8][32])
    ull   AsD[2][CH][8];    // 2 KB
};

template<int K>
__device__ __forceinline__ void gemm64(SmemG& sg, const float* __restrict__ A, int lda, int bm,
                                       const float* __restrict__ W, int ldw, int bn,
                                       ull (&acc)[8]) {
    const int tid = threadIdx.x, w = tid >> 5, lane = tid & 31;
    constexpr int NC = K / CH;
    uint32_t bs_base = (uint32_t)__cvta_generic_to_shared(&sg.Bs[0][0][0]);
    const int ak = tid >> 3, ar = tid & 7;

    #define STAGE_B(c, buf) do {                                                 \
        const float* _src = W + (size_t)((c)*CH)*ldw + bn;                       \
        _Pragma("unroll")                                                        \
        for (int _j = 0; _j < 2; _j++) {                                         \
            int _idx = tid + _j*128;                                             \
            int _kk = _idx >> 4, _q = _idx & 15;                                 \
            cpasync16(bs_base + (uint32_t)(((buf)*CH + _kk)*64 + (_q<<2))*4u,    \
                      _src + (size_t)_kk*ldw + (_q<<2));                         \
        }                                                                        \
        cpcommit();                                                              \
    } while (0)

    STAGE_B(0, 0);
    {
        float aCur = A[(size_t)(bm + ar)*lda + ak];
        sg.AsD[0][ak][ar] = pack2(aCur, aCur);
    }
    #pragma unroll
    for (int r = 0; r < 8; r++) acc[r] = 0ull;

    #pragma unroll 1
    for (int c = 0; c < NC; c++) {
        float aNext = 0.f;
        if (c + 1 < NC) {
            STAGE_B(c+1, (c+1)&1);
            aNext = A[(size_t)(bm + ar)*lda + (c+1)*CH + ak];
            cpwait<1>();
        } else {
            cpwait<0>();
        }
        __syncthreads();
        const int buf = c & 1;
        #pragma unroll
        for (int j = 0; j < CH/4; j++) {
            const int kk = (w << 2) + j;
            const ull* ad = &sg.AsD[buf][kk][0];
            ulonglong2 a01 = *(const ulonglong2*)(ad);
            ulonglong2 a23 = *(const ulonglong2*)(ad + 2);
            ulonglong2 a45 = *(const ulonglong2*)(ad + 4);
            ulonglong2 a67 = *(const ulonglong2*)(ad + 6);
            ull b = *(const ull*)&sg.Bs[buf][kk][lane << 1];
            acc[0] = fma2(a01.x, b, acc[0]);
            acc[1] = fma2(a01.y, b, acc[1]);
            acc[2] = fma2(a23.x, b, acc[2]);
            acc[3] = fma2(a23.y, b, acc[3]);
            acc[4] = fma2(a45.x, b, acc[4]);
            acc[5] = fma2(a45.y, b, acc[5]);
            acc[6] = fma2(a67.x, b, acc[6]);
            acc[7] = fma2(a67.y, b, acc[7]);
        }
        if (c + 1 < NC) sg.AsD[(c+1)&1][ak][ar] = pack2(aNext, aNext);
        __syncthreads();
    }
    #undef STAGE_B
}

// reduce 4 warps' partials; thread gets rows (tid>>5) and (tid>>5)+4, colpair tid&31
__device__ __forceinline__ void gemm64_red(SmemG& sg, ull (&acc)[8], ull& s0, ull& s1) {
    const int tid = threadIdx.x, w = tid >> 5, lane = tid & 31;
    ull (*Red)[8][32] = (ull (*)[8][32])&sg.Bs[0][0][0];
    #pragma unroll
    for (int r = 0; r < 8; r++) Red[w][r][lane] = acc[r];
    __syncthreads();
    const int r0 = tid >> 5, cl = tid & 31;
    s0 = add2(add2(Red[0][r0][cl],   Red[1][r0][cl]),   add2(Red[2][r0][cl],   Red[3][r0][cl]));
    s1 = add2(add2(Red[0][r0+4][cl], Red[1][r0+4][cl]), add2(Red[2][r0+4][cl], Red[3][r0+4][cl]));
}

// ---------------- r/k/v GEMMs: grid (2, 128, 3), 128 thr ----------------
__global__ void __launch_bounds__(128)
rkv_kernel(const float* __restrict__ hs,
           const float* __restrict__ Wr, const float* __restrict__ br,
           const float* __restrict__ Wk, const float* __restrict__ bk,
           const float* __restrict__ Wv, const float* __restrict__ bv,
           float* __restrict__ ro, float* __restrict__ ko, float* __restrict__ vo) {
    __shared__ SmemG sg;
    const int z = blockIdx.z;
    const float* W  = (z == 0) ? Wr : (z == 1) ? Wk : Wv;
    const float* bb = (z == 0) ? br : (z == 1) ? bk : bv;
    float* o        = (z == 0) ? ro : (z == 1) ? ko : vo;
    const int bn = blockIdx.x << 6, bm = blockIdx.y << 3;
    ull acc[8];
    gemm64<CC>(sg, hs, CC, bm, W, CC, bn, acc);
    ull s0, s1;
    gemm64_red(sg, acc, s0, s1);
    const int r0 = threadIdx.x >> 5, cl = threadIdx.x & 31;
    const int col = bn + (cl << 1);
    float2 bias = *(const float2*)(bb + col);
    #pragma unroll
    for (int i = 0; i < 2; i++) {
        int m = bm + r0 + i*4;
        float x0, x1; unpack2(i ? s1 : s0, x0, x1);
        x0 += bias.x; x1 += bias.y;
        if (z == 0) { x0 = 1.0f/(1.0f+expf(-x0)); x1 = 1.0f/(1.0f+expf(-x1)); }
        *(float2*)(o + (size_t)m*CC + col) = make_float2(x0, x1);
    }
}

// ---------------- WKV (round-5, proven): 128 blocks x 1024 thr ----------------
__global__ void __launch_bounds__(1024, 1)
wkv_kernel(const float* __restrict__ k, const float* __restrict__ v,
           const float* __restrict__ r, const float* __restrict__ wd,
           float* __restrict__ wk) {
    __shared__ float s_acc[4][8][CC];
    const int tid = threadIdx.x;
    const int wid = tid >> 5, lane = tid & 31;
    const int seg = wid >> 3, rloc = wid & 7;
    const int row = (blockIdx.x << 3) + rloc;
    const int bb  = row >> 9;
    const int h = lane >> 4, p = lane & 15;
    const int c0 = p << 3;

    float bv8[8];
    {
        float4 k0 = *(const float4*)(k  + (size_t)row*CC + c0);
        float4 k1 = *(const float4*)(k  + (size_t)row*CC + c0 + 4);
        float4 w0 = *(const float4*)(wd + c0);
        float4 w1 = *(const float4*)(wd + c0 + 4);
        bv8[0] = k0.x * (-expf(w0.x)); bv8[1] = k0.y * (-expf(w0.y));
        bv8[2] = k0.z * (-expf(w0.z)); bv8[3] = k0.w * (-expf(w0.w));
        bv8[4] = k1.x * (-expf(w1.x)); bv8[5] = k1.y * (-expf(w1.y));
        bv8[6] = k1.z * (-expf(w1.z)); bv8[7] = k1.w * (-expf(w1.w));
    }
    float amax = bv8[0];
    #pragma unroll
    for (int i = 1; i < 8; i++) amax = fmaxf(amax, bv8[i]);
    #pragma unroll
    for (int o = 16; o; o >>= 1) amax = fmaxf(amax, __shfl_xor_sync(0xffffffffu, amax, o));
    #pragma unroll
    for (int i = 0; i < 8; i++) bv8[i] -= amax;

    const float inv511 = 1.0f/511.0f;
    const int l0 = seg << 7;
    const float s0 = (float)(511 - (l0 + h)) * inv511;
    ull E2[4], g2[4];
    #pragma unroll
    for (int j = 0; j < 4; j++) {
        E2[j] = pack2(expf(bv8[2*j]*s0),           expf(bv8[2*j+1]*s0));
        g2[j] = pack2(expf(-2.0f*bv8[2*j]*inv511), expf(-2.0f*bv8[2*j+1]*inv511));
    }
    ull acc2[4] = {0ull, 0ull, 0ull, 0ull};
    const float* vp = v + ((size_t)(bb << 9) + l0 + h)*CC + c0;

    #pragma unroll 4
    for (int i = 0; i < 64; i++) {
        ull t = add2(add2(E2[0], E2[1]), add2(E2[2], E2[3]));
        float zl, zh; unpack2(t, zl, zh);
        float z = zl + zh;
        #pragma unroll
        for (int o = 8; o; o >>= 1) z += __shfl_xor_sync(0xffffffffu, z, o);
        float inv = rcpa(z + 1e-6f);
        ull invd = pack2(inv, inv);
        ulonglong2 v01 = *(const ulonglong2*)(vp);
        ulonglong2 v23 = *(const ulonglong2*)(vp + 4);
        acc2[0] = fma2(mul2(E2[0], invd), v01.x, acc2[0]);
        acc2[1] = fma2(mul2(E2[1], invd), v01.y, acc2[1]);
        acc2[2] = fma2(mul2(E2[2], invd), v23.x, acc2[2]);
        acc2[3] = fma2(mul2(E2[3], invd), v23.y, acc2[3]);
        E2[0] = mul2(E2[0], g2[0]); E2[1] = mul2(E2[1], g2[1]);
        E2[2] = mul2(E2[2], g2[2]); E2[3] = mul2(E2[3], g2[3]);
        vp += 2*CC;
    }

    #pragma unroll
    for (int j = 0; j < 4; j++) {
        float x, y; unpack2(acc2[j], x, y);
        x += __shfl_xor_sync(0xffffffffu, x, 16);
        y += __shfl_xor_sync(0xffffffffu, y, 16);
        if (h == 0) {
            s_acc[seg][rloc][c0 + 2*j    ] = x;
            s_acc[seg][rloc][c0 + 2*j + 1] = y;
        }
    }
    __syncthreads();

    const int rl = tid >> 7, c = tid & (CC-1);
    float sum = (s_acc[0][rl][c] + s_acc[1][rl][c]) + (s_acc[2][rl][c] + s_acc[3][rl][c]);
    const int grow = (blockIdx.x << 3) + rl;
    wk[(size_t)grow*CC + c] = r[(size_t)grow*CC + c] * sum;
}

// ---------------- Wo GEMM + bias + residual -> y : grid (2, 128) ----------------
__global__ void __launch_bounds__(128)
wo_kernel(const float* __restrict__ wkin, const float* __restrict__ Wo,
          const float* __restrict__ bo, const float* __restrict__ x,
          float* __restrict__ y) {
    __shared__ SmemG sg;
    const int bn = blockIdx.x << 6, bm = blockIdx.y << 3;
    ull acc[8];
    gemm64<CC>(sg, wkin, CC, bm, Wo, CC, bn, acc);
    ull s0, s1;
    gemm64_red(sg, acc, s0, s1);
    const int r0 = threadIdx.x >> 5, cl = threadIdx.x & 31;
    const int col = bn + (cl << 1);
    float2 bias = *(const float2*)(bo + col);
    #pragma unroll
    for (int i = 0; i < 2; i++) {
        int m = bm + r0 + i*4;
        float x0, x1; unpack2(i ? s1 : s0, x0, x1);
        float2 xv = *(const float2*)(x + (size_t)m*CC + col);
        *(float2*)(y + (size_t)m*CC + col) = make_float2(x0 + bias.x + xv.x, x1 + bias.y + xv.y);
    }
}

// ---------------- LN2: y -> h2 : grid 128, 256 thr (warp = row) ----------------
__global__ void __launch_bounds__(256)
ln2_kernel(const float* __restrict__ y, const float* __restrict__ gam,
           const float* __restrict__ bet, float* __restrict__ h2) {
    const int tid = threadIdx.x, w = tid >> 5, lane = tid & 31;
    const int row = (blockIdx.x << 3) + w;
    float4 g4 = *(const float4*)(gam + (lane << 2));
    float4 b4 = *(const float4*)(bet + (lane << 2));
    float4 yv = *(const float4*)(y + (size_t)row*CC + (lane << 2));
    float mean = wsum((yv.x + yv.y) + (yv.z + yv.w)) * (1.0f/CC);
    float d0 = yv.x - mean, d1 = yv.y - mean, d2 = yv.z - mean, d3 = yv.w - mean;
    float rs = rsqrtf(wsum((d0*d0 + d1*d1) + (d2*d2 + d3*d3)) * (1.0f/CC) + 1e-5f);
    *(float4*)(h2 + (size_t)row*CC + (lane << 2)) =
        make_float4(d0*rs*g4.x + b4.x, d1*rs*g4.y + b4.y,
                    d2*rs*g4.z + b4.z, d3*rs*g4.w + b4.w);
}

// ---------------- W1 GEMM + exact gelu : grid (8, 128) ----------------
__global__ void __launch_bounds__(128)
w1_kernel(const float* __restrict__ h2, const float* __restrict__ W1,
          const float* __restrict__ b1, float* __restrict__ mid) {
    __shared__ SmemG sg;
    const int bn = blockIdx.x << 6, bm = blockIdx.y << 3;
    ull acc[8];
    gemm64<CC>(sg, h2, CC, bm, W1, HH, bn, acc);
    ull s0, s1;
    gemm64_red(sg, acc, s0, s1);
    const int r0 = threadIdx.x >> 5, cl = threadIdx.x & 31;
    const int col = bn + (cl << 1);
    float2 bias = *(const float2*)(b1 + col);
    const float gc = 0.70710678118654752f;
    #pragma unroll
    for (int i = 0; i < 2; i++) {
        int m = bm + r0 + i*4;
        float x0, x1; unpack2(i ? s1 : s0, x0, x1);
        x0 += bias.x; x1 += bias.y;
        x0 = 0.5f*x0*(1.0f + erff(x0*gc));
        x1 = 0.5f*x1*(1.0f + erff(x1*gc));
        *(float2*)(mid + (size_t)m*HH + col) = make_float2(x0, x1);
    }
}

// ---------------- W2 GEMM (K=512) + bias + residual -> out : grid (2, 128) ----------------
__global__ void __launch_bounds__(128)
w2_kernel(const float* __restrict__ mid, const float* __restrict__ W2,
          const float* __restrict__ b2, const float* __restrict__ y,
          float* __restrict__ out) {
    __shared__ SmemG sg;
    const int bn = blockIdx.x << 6, bm = blockIdx.y << 3;
    ull acc[8];
    gemm64<HH>(sg, mid, HH, bm, W2, CC, bn, acc);
    ull s0, s1;
    gemm64_red(sg, acc, s0, s1);
    const int r0 = threadIdx.x >> 5, cl = threadIdx.x & 31;
    const int col = bn + (cl << 1);
    float2 bias = *(const float2*)(b2 + col);
    #pragma unroll
    for (int i = 0; i < 2; i++) {
        int m = bm + r0 + i*4;
        float x0, x1; unpack2(i ? s1 : s0, x0, x1);
        float2 yv = *(const float2*)(y + (size_t)m*CC + col);
        *(float2*)(out + (size_t)m*CC + col) = make_float2(x0 + bias.x + yv.x, x1 + bias.y + yv.y);
    }
}

// ---------------- launch ----------------
extern "C" void kernel_launch(void* const* d_in, const int* in_sizes, int n_in,
                              void* d_out, int out_size) {
    const float* x       = (const float*)d_in[0];
    const float* ln1_g   = (const float*)d_in[1];
    const float* ln1_b   = (const float*)d_in[2];
    const float* mu      = (const float*)d_in[3];
    const float* Wr      = (const float*)d_in[4];
    const float* br      = (const float*)d_in[5];
    const float* Wk      = (const float*)d_in[6];
    const float* bk      = (const float*)d_in[7];
    const float* Wv      = (const float*)d_in[8];
    const float* bv      = (const float*)d_in[9];
    const float* w_decay = (const float*)d_in[10];
    const float* Wo      = (const float*)d_in[11];
    const float* bo      = (const float*)d_in[12];
    const float* ln2_g   = (const float*)d_in[13];
    const float* ln2_b   = (const float*)d_in[14];
    const float* W1      = (const float*)d_in[15];
    const float* b1      = (const float*)d_in[16];
    const float* W2      = (const float*)d_in[17];
    const float* b2      = (const float*)d_in[18];
    float* out = (float*)d_out;

    float *hs, *r_, *k_, *v_, *wkp, *y, *h2, *mid;
    cudaGetSymbolAddress((void**)&hs,  g_hs);
    cudaGetSymbolAddress((void**)&r_,  g_r);
    cudaGetSymbolAddress((void**)&k_,  g_k);
    cudaGetSymbolAddress((void**)&v_,  g_v);
    cudaGetSymbolAddress((void**)&wkp, g_wk);
    cudaGetSymbolAddress((void**)&y,   g_y);
    cudaGetSymbolAddress((void**)&h2,  g_h2);
    cudaGetSymbolAddress((void**)&mid, g_mid);

    ln_shift_kernel<<<128, 256>>>(x, ln1_g, ln1_b, mu, hs);
    rkv_kernel<<<dim3(2, 128, 3), 128>>>(hs, Wr, br, Wk, bk, Wv, bv, r_, k_, v_);
    wkv_kernel<<<128, 1024>>>(k_, v_, r_, w_decay, wkp);
    wo_kernel<<<dim3(2, 128), 128>>>(wkp, Wo, bo, x, y);
    ln2_kernel<<<128, 256>>>(y, ln2_g, ln2_b, h2);
    w1_kernel<<<dim3(8, 128), 128>>>(h2, W1, b1, mid);
    w2_kernel<<<dim3(2, 128), 128>>>(mid, W2, b2, y, out);
}

// round 10
// speedup vs baseline: 1.2097x; 1.0211x over previous
#include <cuda_runtime.h>
#include <math.h>
#include <stdint.h>

#define TT 512
#define CC 128
#define HH 512
#define ROWS 1024
#define CH 16

// ---------------- scratch ----------------
__device__ float g_hs [ROWS*CC];
__device__ float g_r  [ROWS*CC];
__device__ float g_k  [ROWS*CC];
__device__ float g_v  [ROWS*CC];
__device__ float g_wk [ROWS*CC];
__device__ float g_y  [ROWS*CC];
__device__ float g_h2 [ROWS*CC];
__device__ float g_mid[ROWS*HH];

// ---------------- helpers ----------------
__device__ __forceinline__ float wsum(float x) {
    #pragma unroll
    for (int o = 16; o; o >>= 1) x += __shfl_xor_sync(0xffffffffu, x, o);
    return x;
}
__device__ __forceinline__ float rcpa(float x) {
    float r; asm("rcp.approx.f32 %0, %1;" : "=f"(r) : "f"(x)); return r;
}
typedef unsigned long long ull;
__device__ __forceinline__ ull pack2(float x, float y) {
    ull r; asm("mov.b64 %0, {%1, %2};" : "=l"(r) : "f"(x), "f"(y)); return r;
}
__device__ __forceinline__ void unpack2(ull p, float& x, float& y) {
    asm("mov.b64 {%0, %1}, %2;" : "=f"(x), "=f"(y) : "l"(p));
}
__device__ __forceinline__ ull fma2(ull a, ull b, ull c) {
    ull d; asm("fma.rn.f32x2 %0, %1, %2, %3;" : "=l"(d) : "l"(a), "l"(b), "l"(c)); return d;
}
__device__ __forceinline__ ull mul2(ull a, ull b) {
    ull d; asm("mul.rn.f32x2 %0, %1, %2;" : "=l"(d) : "l"(a), "l"(b)); return d;
}
__device__ __forceinline__ ull add2(ull a, ull b) {
    ull d; asm("add.rn.f32x2 %0, %1, %2;" : "=l"(d) : "l"(a), "l"(b)); return d;
}
__device__ __forceinline__ void cpasync16(uint32_t saddr, const void* g) {
    asm volatile("cp.async.ca.shared.global [%0], [%1], 16;" :: "r"(saddr), "l"(g));
}
__device__ __forceinline__ void cpcommit() { asm volatile("cp.async.commit_group;"); }
template<int N> __device__ __forceinline__ void cpwait() {
    asm volatile("cp.async.wait_group %0;" :: "n"(N));
}

// ---------------- fused LN1 + TemporalShift (proven) ----------------
__global__ void __launch_bounds__(256)
ln_shift_kernel(const float* __restrict__ x,
                const float* __restrict__ gam, const float* __restrict__ bet,
                const float* __restrict__ mu, float* __restrict__ hs) {
    __shared__ float sh[10][CC];
    const int tid = threadIdx.x;
    const int w = tid >> 5, lane = tid & 31;
    const int b  = blockIdx.x >> 6;
    const int t0 = (blockIdx.x & 63) << 3;

    float4 g4 = *(const float4*)(gam + (lane << 2));
    float4 b4 = *(const float4*)(bet + (lane << 2));

    for (int hr = w; hr < 10; hr += 8) {
        int t = t0 - 1 + hr;
        bool ok = (t >= 0) && (t < TT);
        float4 xv = make_float4(0.f, 0.f, 0.f, 0.f);
        if (ok) xv = *(const float4*)(x + (size_t)((b << 9) + t)*CC + (lane << 2));
        float mean = wsum((xv.x + xv.y) + (xv.z + xv.w)) * (1.0f/CC);
        float d0 = xv.x - mean, d1 = xv.y - mean, d2 = xv.z - mean, d3 = xv.w - mean;
        float rs = rsqrtf(wsum((d0*d0 + d1*d1) + (d2*d2 + d3*d3)) * (1.0f/CC) + 1e-5f);
        int c = lane << 2;
        sh[hr][c+0] = ok ? d0*rs*g4.x + b4.x : 0.f;
        sh[hr][c+1] = ok ? d1*rs*g4.y + b4.y : 0.f;
        sh[hr][c+2] = ok ? d2*rs*g4.z + b4.z : 0.f;
        sh[hr][c+3] = ok ? d3*rs*g4.w + b4.w : 0.f;
    }
    __syncthreads();
    for (int i = tid; i < 8*CC; i += 256) {
        int rl = i >> 7, c = i & (CC-1);
        float val = sh[rl+1][c];
        float shv = (c < CC/2) ? sh[rl][c] : sh[rl+2][c];
        hs[(size_t)((b << 9) + t0 + rl)*CC + c] = val + mu[c]*shv;
    }
}

// ================= GEMM64 v2: 8 rows x 64 cols, 128 thr, A hoisted =================
// A dup-packed once per 128-k segment into k-major smem (warp-broadcast reads).
// B streamed through a 3-deep cp.async ring. Mainloop has ZERO global accesses.
struct __align__(16) SmemG64 {
    ull   Ad[128][8];       //  8 KB (k-major dup-A for current segment)
    float Bs[3][CH][64];    // 12 KB; Bs[0..1] alias Red ull[4][8][32] (8 KB)
};

template<int K>
__device__ __forceinline__ void gemm64(SmemG64& sg, const float* __restrict__ A, int lda, int bm,
                                       const float* __restrict__ W, int ldw, int bn,
                                       ull (&acc)[8]) {
    const int tid = threadIdx.x, w = tid >> 5, lane = tid & 31;
    constexpr int NCHUNK = K / CH;
    constexpr int NSEG = K / 128;
    uint32_t bs_base = (uint32_t)__cvta_generic_to_shared(&sg.Bs[0][0][0]);

    #define STAGE_B64(c) do {                                                    \
        int _buf = (c) % 3;                                                      \
        const float* _src = W + (size_t)((c)*CH)*ldw + bn;                       \
        _Pragma("unroll")                                                        \
        for (int _j = 0; _j < 2; _j++) {                                         \
            int _idx = tid + _j*128;                                             \
            int _kk = _idx >> 4, _q = _idx & 15;                                 \
            cpasync16(bs_base + (uint32_t)((_buf*CH + _kk)*64 + (_q<<2))*4u,     \
                      _src + (size_t)_kk*ldw + (_q<<2));                         \
        }                                                                        \
        cpcommit();                                                              \
    } while (0)

    // prefetch A segment 0 (thread = k column; coalesced per row)
    float areg[8];
    #pragma unroll
    for (int r = 0; r < 8; r++) areg[r] = A[(size_t)(bm + r)*lda + tid];

    STAGE_B64(0); STAGE_B64(1); STAGE_B64(2);

    #pragma unroll
    for (int r = 0; r < 8; r++) acc[r] = 0ull;

    #pragma unroll 1
    for (int seg = 0; seg < NSEG; seg++) {
        if (seg > 0) __syncthreads();               // prior segment's Ad reads done
        {   // store dup-A, k-major: Ad[tid][0..7]
            ulonglong2* dst = (ulonglong2*)&sg.Ad[tid][0];
            dst[0] = make_ulonglong2(pack2(areg[0], areg[0]), pack2(areg[1], areg[1]));
            dst[1] = make_ulonglong2(pack2(areg[2], areg[2]), pack2(areg[3], areg[3]));
            dst[2] = make_ulonglong2(pack2(areg[4], areg[4]), pack2(areg[5], areg[5]));
            dst[3] = make_ulonglong2(pack2(areg[6], areg[6]), pack2(areg[7], areg[7]));
        }
        if (seg + 1 < NSEG) {                       // prefetch next segment (hidden)
            #pragma unroll
            for (int r = 0; r < 8; r++)
                areg[r] = A[(size_t)(bm + r)*lda + (seg + 1)*128 + tid];
        }
        __syncthreads();                            // Ad visible

        #pragma unroll 1
        for (int cc = 0; cc < 8; cc++) {
            const int c = seg*8 + cc;
            if (c + 1 < NCHUNK) cpwait<1>(); else cpwait<0>();
            __syncthreads();                        // chunk c ready; chunk c-1 compute done
            if (c + 2 < NCHUNK) STAGE_B64(c + 2);   // buf (c+2)%3 == (c-1)%3: safe
            const int buf = c % 3;
            #pragma unroll
            for (int j = 0; j < 4; j++) {
                const int kk = (w << 2) + j;        // k within chunk
                const ull* ad = &sg.Ad[(cc << 4) + kk][0];
                ulonglong2 a01 = *(const ulonglong2*)(ad);
                ulonglong2 a23 = *(const ulonglong2*)(ad + 2);
                ulonglong2 a45 = *(const ulonglong2*)(ad + 4);
                ulonglong2 a67 = *(const ulonglong2*)(ad + 6);
                ull b = *(const ull*)&sg.Bs[buf][kk][lane << 1];
                acc[0] = fma2(a01.x, b, acc[0]);
                acc[1] = fma2(a01.y, b, acc[1]);
                acc[2] = fma2(a23.x, b, acc[2]);
                acc[3] = fma2(a23.y, b, acc[3]);
                acc[4] = fma2(a45.x, b, acc[4]);
                acc[5] = fma2(a45.y, b, acc[5]);
                acc[6] = fma2(a67.x, b, acc[6]);
                acc[7] = fma2(a67.y, b, acc[7]);
            }
        }
    }
    #undef STAGE_B64
}

// reduce 4 warps' split-K partials; thread gets rows (tid>>5), (tid>>5)+4, colpair tid&31
__device__ __forceinline__ void gemm64_red(SmemG64& sg, ull (&acc)[8], ull& s0, ull& s1) {
    const int tid = threadIdx.x, w = tid >> 5, lane = tid & 31;
    ull (*Red)[8][32] = (ull (*)[8][32])&sg.Bs[0][0][0];
    __syncthreads();                                // all compute done before alias write
    #pragma unroll
    for (int r = 0; r < 8; r++) Red[w][r][lane] = acc[r];
    __syncthreads();
    const int r0 = tid >> 5, cl = tid & 31;
    s0 = add2(add2(Red[0][r0][cl],   Red[1][r0][cl]),   add2(Red[2][r0][cl],   Red[3][r0][cl]));
    s1 = add2(add2(Red[0][r0+4][cl], Red[1][r0+4][cl]), add2(Red[2][r0+4][cl], Red[3][r0+4][cl]));
}

// ---------------- r/k/v GEMMs: grid (2, 128, 3), 128 thr ----------------
__global__ void __launch_bounds__(128)
rkv_kernel(const float* __restrict__ hs,
           const float* __restrict__ Wr, const float* __restrict__ br,
           const float* __restrict__ Wk, const float* __restrict__ bk,
           const float* __restrict__ Wv, const float* __restrict__ bv,
           float* __restrict__ ro, float* __restrict__ ko, float* __restrict__ vo) {
    __shared__ SmemG64 sg;
    const int z = blockIdx.z;
    const float* W  = (z == 0) ? Wr : (z == 1) ? Wk : Wv;
    const float* bb = (z == 0) ? br : (z == 1) ? bk : bv;
    float* o        = (z == 0) ? ro : (z == 1) ? ko : vo;
    const int bn = blockIdx.x << 6, bm = blockIdx.y << 3;
    ull acc[8];
    gemm64<CC>(sg, hs, CC, bm, W, CC, bn, acc);
    ull s0, s1;
    gemm64_red(sg, acc, s0, s1);
    const int r0 = threadIdx.x >> 5, cl = threadIdx.x & 31;
    const int col = bn + (cl << 1);
    float2 bias = *(const float2*)(bb + col);
    #pragma unroll
    for (int i = 0; i < 2; i++) {
        int m = bm + r0 + i*4;
        float x0, x1; unpack2(i ? s1 : s0, x0, x1);
        x0 += bias.x; x1 += bias.y;
        if (z == 0) { x0 = 1.0f/(1.0f+expf(-x0)); x1 = 1.0f/(1.0f+expf(-x1)); }
        *(float2*)(o + (size_t)m*CC + col) = make_float2(x0, x1);
    }
}

// ---------------- WKV (proven): 128 blocks x 1024 thr ----------------
__global__ void __launch_bounds__(1024, 1)
wkv_kernel(const float* __restrict__ k, const float* __restrict__ v,
           const float* __restrict__ r, const float* __restrict__ wd,
           float* __restrict__ wk) {
    __shared__ float s_acc[4][8][CC];
    const int tid = threadIdx.x;
    const int wid = tid >> 5, lane = tid & 31;
    const int seg = wid >> 3, rloc = wid & 7;
    const int row = (blockIdx.x << 3) + rloc;
    const int bb  = row >> 9;
    const int h = lane >> 4, p = lane & 15;
    const int c0 = p << 3;

    float bv8[8];
    {
        float4 k0 = *(const float4*)(k  + (size_t)row*CC + c0);
        float4 k1 = *(const float4*)(k  + (size_t)row*CC + c0 + 4);
        float4 w0 = *(const float4*)(wd + c0);
        float4 w1 = *(const float4*)(wd + c0 + 4);
        bv8[0] = k0.x * (-expf(w0.x)); bv8[1] = k0.y * (-expf(w0.y));
        bv8[2] = k0.z * (-expf(w0.z)); bv8[3] = k0.w * (-expf(w0.w));
        bv8[4] = k1.x * (-expf(w1.x)); bv8[5] = k1.y * (-expf(w1.y));
        bv8[6] = k1.z * (-expf(w1.z)); bv8[7] = k1.w * (-expf(w1.w));
    }
    float amax = bv8[0];
    #pragma unroll
    for (int i = 1; i < 8; i++) amax = fmaxf(amax, bv8[i]);
    #pragma unroll
    for (int o = 16; o; o >>= 1) amax = fmaxf(amax, __shfl_xor_sync(0xffffffffu, amax, o));
    #pragma unroll
    for (int i = 0; i < 8; i++) bv8[i] -= amax;

    const float inv511 = 1.0f/511.0f;
    const int l0 = seg << 7;
    const float s0 = (float)(511 - (l0 + h)) * inv511;
    ull E2[4], g2[4];
    #pragma unroll
    for (int j = 0; j < 4; j++) {
        E2[j] = pack2(expf(bv8[2*j]*s0),           expf(bv8[2*j+1]*s0));
        g2[j] = pack2(expf(-2.0f*bv8[2*j]*inv511), expf(-2.0f*bv8[2*j+1]*inv511));
    }
    ull acc2[4] = {0ull, 0ull, 0ull, 0ull};
    const float* vp = v + ((size_t)(bb << 9) + l0 + h)*CC + c0;

    #pragma unroll 4
    for (int i = 0; i < 64; i++) {
        ull t = add2(add2(E2[0], E2[1]), add2(E2[2], E2[3]));
        float zl, zh; unpack2(t, zl, zh);
        float z = zl + zh;
        #pragma unroll
        for (int o = 8; o; o >>= 1) z += __shfl_xor_sync(0xffffffffu, z, o);
        float inv = rcpa(z + 1e-6f);
        ull invd = pack2(inv, inv);
        ulonglong2 v01 = *(const ulonglong2*)(vp);
        ulonglong2 v23 = *(const ulonglong2*)(vp + 4);
        acc2[0] = fma2(mul2(E2[0], invd), v01.x, acc2[0]);
        acc2[1] = fma2(mul2(E2[1], invd), v01.y, acc2[1]);
        acc2[2] = fma2(mul2(E2[2], invd), v23.x, acc2[2]);
        acc2[3] = fma2(mul2(E2[3], invd), v23.y, acc2[3]);
        E2[0] = mul2(E2[0], g2[0]); E2[1] = mul2(E2[1], g2[1]);
        E2[2] = mul2(E2[2], g2[2]); E2[3] = mul2(E2[3], g2[3]);
        vp += 2*CC;
    }

    #pragma unroll
    for (int j = 0; j < 4; j++) {
        float x, y; unpack2(acc2[j], x, y);
        x += __shfl_xor_sync(0xffffffffu, x, 16);
        y += __shfl_xor_sync(0xffffffffu, y, 16);
        if (h == 0) {
            s_acc[seg][rloc][c0 + 2*j    ] = x;
            s_acc[seg][rloc][c0 + 2*j + 1] = y;
        }
    }
    __syncthreads();

    const int rl = tid >> 7, c = tid & (CC-1);
    float sum = (s_acc[0][rl][c] + s_acc[1][rl][c]) + (s_acc[2][rl][c] + s_acc[3][rl][c]);
    const int grow = (blockIdx.x << 3) + rl;
    wk[(size_t)grow*CC + c] = r[(size_t)grow*CC + c] * sum;
}

// ================= wo_ln: 8 rows x 128 cols, 128 thr, A hoisted, LN2 fused =========
struct __align__(16) SmemW {
    ull   Ad[128][8];        //  8 KB
    float Bs[3][CH][CC];     // 24 KB; Bs[0..1] alias Red ull[4][8][32] (8 KB, two passes)
};

__global__ void __launch_bounds__(128)
wo_ln_kernel(const float* __restrict__ wkin, const float* __restrict__ Wo,
             const float* __restrict__ bo, const float* __restrict__ x,
             const float* __restrict__ g2, const float* __restrict__ be2,
             float* __restrict__ y, float* __restrict__ h2) {
    __shared__ SmemW sg;
    const int tid = threadIdx.x, w = tid >> 5, lane = tid & 31;
    const int bm = blockIdx.x << 3;
    uint32_t bs_base = (uint32_t)__cvta_generic_to_shared(&sg.Bs[0][0][0]);

    #define STAGE_BW(c) do {                                                     \
        int _buf = (c) % 3;                                                      \
        const float* _src = Wo + (size_t)((c)*CH)*CC;                            \
        _Pragma("unroll")                                                        \
        for (int _j = 0; _j < 4; _j++) {                                         \
            int _idx = tid + _j*128;                                             \
            int _kk = _idx >> 5, _q = _idx & 31;                                 \
            cpasync16(bs_base + (uint32_t)((_buf*CH + _kk)*CC + (_q<<2))*4u,     \
                      _src + (size_t)_kk*CC + (_q<<2));                          \
        }                                                                        \
        cpcommit();                                                              \
    } while (0)

    float areg[8];
    #pragma unroll
    for (int r = 0; r < 8; r++) areg[r] = wkin[(size_t)(bm + r)*CC + tid];

    STAGE_BW(0); STAGE_BW(1); STAGE_BW(2);

    {
        ulonglong2* dst = (ulonglong2*)&sg.Ad[tid][0];
        dst[0] = make_ulonglong2(pack2(areg[0], areg[0]), pack2(areg[1], areg[1]));
        dst[1] = make_ulonglong2(pack2(areg[2], areg[2]), pack2(areg[3], areg[3]));
        dst[2] = make_ulonglong2(pack2(areg[4], areg[4]), pack2(areg[5], areg[5]));
        dst[3] = make_ulonglong2(pack2(areg[6], areg[6]), pack2(areg[7], areg[7]));
    }
    __syncthreads();

    ull acc[8][2];
    #pragma unroll
    for (int r = 0; r < 8; r++) { acc[r][0] = 0ull; acc[r][1] = 0ull; }

    #pragma unroll 1
    for (int c = 0; c < 8; c++) {
        if (c + 1 < 8) cpwait<1>(); else cpwait<0>();
        __syncthreads();
        if (c + 2 < 8) STAGE_BW(c + 2);
        const int buf = c % 3;
        #pragma unroll
        for (int j = 0; j < 4; j++) {
            const int kk = (w << 2) + j;
            const ull* ad = &sg.Ad[(c << 4) + kk][0];
            ulonglong2 a01 = *(const ulonglong2*)(ad);
            ulonglong2 a23 = *(const ulonglong2*)(ad + 2);
            ulonglong2 a45 = *(const ulonglong2*)(ad + 4);
            ulonglong2 a67 = *(const ulonglong2*)(ad + 6);
            ull b0 = *(const ull*)&sg.Bs[buf][kk][lane << 1];
            ull b1 = *(const ull*)&sg.Bs[buf][kk][(lane + 32) << 1];
            acc[0][0]=fma2(a01.x,b0,acc[0][0]); acc[0][1]=fma2(a01.x,b1,acc[0][1]);
            acc[1][0]=fma2(a01.y,b0,acc[1][0]); acc[1][1]=fma2(a01.y,b1,acc[1][1]);
            acc[2][0]=fma2(a23.x,b0,acc[2][0]); acc[2][1]=fma2(a23.x,b1,acc[2][1]);
            acc[3][0]=fma2(a23.y,b0,acc[3][0]); acc[3][1]=fma2(a23.y,b1,acc[3][1]);
            acc[4][0]=fma2(a45.x,b0,acc[4][0]); acc[4][1]=fma2(a45.x,b1,acc[4][1]);
            acc[5][0]=fma2(a45.y,b0,acc[5][0]); acc[5][1]=fma2(a45.y,b1,acc[5][1]);
            acc[6][0]=fma2(a67.x,b0,acc[6][0]); acc[6][1]=fma2(a67.x,b1,acc[6][1]);
            acc[7][0]=fma2(a67.y,b0,acc[7][0]); acc[7][1]=fma2(a67.y,b1,acc[7][1]);
        }
    }
    #undef STAGE_BW

    // split-K reduce in two passes (Red = 8 KB alias over Bs[0..1]).
    // Thread (warp w, lane cl) ends owning rows {2w, 2w+1}, cols {2cl,2cl+1, 64+2cl,64+2cl+1}.
    ull (*Red)[8][32] = (ull (*)[8][32])&sg.Bs[0][0][0];
    ull sa[2], sb[2];
    #pragma unroll
    for (int pp = 0; pp < 2; pp++) {
        __syncthreads();
        #pragma unroll
        for (int r = 0; r < 8; r++) Red[w][r][lane] = acc[r][pp];
        __syncthreads();
        const int cl = lane;
        sa[pp] = add2(add2(Red[0][2*w  ][cl], Red[1][2*w  ][cl]),
                      add2(Red[2][2*w  ][cl], Red[3][2*w  ][cl]));
        sb[pp] = add2(add2(Red[0][2*w+1][cl], Red[1][2*w+1][cl]),
                      add2(Red[2][2*w+1][cl], Red[3][2*w+1][cl]));
    }

    const int cl = lane;
    #pragma unroll
    for (int rr = 0; rr < 2; rr++) {
        int m = bm + 2*w + rr;
        float v0, v1, v2, v3;
        unpack2(rr ? sb[0] : sa[0], v0, v1);   // cols 2cl, 2cl+1
        unpack2(rr ? sb[1] : sa[1], v2, v3);   // cols 64+2cl, 64+2cl+1
        float2 bo0 = *(const float2*)(bo + (cl << 1));
        float2 bo1 = *(const float2*)(bo + 64 + (cl << 1));
        float2 xv0 = *(const float2*)(x + (size_t)m*CC + (cl << 1));
        float2 xv1 = *(const float2*)(x + (size_t)m*CC + 64 + (cl << 1));
        float y0 = v0 + bo0.x + xv0.x;
        float y1 = v1 + bo0.y + xv0.y;
        float y2 = v2 + bo1.x + xv1.x;
        float y3 = v3 + bo1.y + xv1.y;
        *(float2*)(y + (size_t)m*CC + (cl << 1))      = make_float2(y0, y1);
        *(float2*)(y + (size_t)m*CC + 64 + (cl << 1)) = make_float2(y2, y3);
        float mean = wsum((y0 + y1) + (y2 + y3)) * (1.0f/CC);
        float d0 = y0 - mean, d1 = y1 - mean, d2 = y2 - mean, d3 = y3 - mean;
        float rs = rsqrtf(wsum((d0*d0 + d1*d1) + (d2*d2 + d3*d3)) * (1.0f/CC) + 1e-5f);
        float2 ga0 = *(const float2*)(g2 + (cl << 1));
        float2 ga1 = *(const float2*)(g2 + 64 + (cl << 1));
        float2 be0 = *(const float2*)(be2 + (cl << 1));
        float2 be1 = *(const float2*)(be2 + 64 + (cl << 1));
        *(float2*)(h2 + (size_t)m*CC + (cl << 1)) =
            make_float2(d0*rs*ga0.x + be0.x, d1*rs*ga0.y + be0.y);
        *(float2*)(h2 + (size_t)m*CC + 64 + (cl << 1)) =
            make_float2(d2*rs*ga1.x + be1.x, d3*rs*ga1.y + be1.y);
    }
}

// ---------------- W1 GEMM + exact gelu : grid (8, 128), 128 thr ----------------
__global__ void __launch_bounds__(128)
w1_kernel(const float* __restrict__ h2, const float* __restrict__ W1,
          const float* __restrict__ b1, float* __restrict__ mid) {
    __shared__ SmemG64 sg;
    const int bn = blockIdx.x << 6, bm = blockIdx.y << 3;
    ull acc[8];
    gemm64<CC>(sg, h2, CC, bm, W1, HH, bn, acc);
    ull s0, s1;
    gemm64_red(sg, acc, s0, s1);
    const int r0 = threadIdx.x >> 5, cl = threadIdx.x & 31;
    const int col = bn + (cl << 1);
    float2 bias = *(const float2*)(b1 + col);
    const float gc = 0.70710678118654752f;
    #pragma unroll
    for (int i = 0; i < 2; i++) {
        int m = bm + r0 + i*4;
        float x0, x1; unpack2(i ? s1 : s0, x0, x1);
        x0 += bias.x; x1 += bias.y;
        x0 = 0.5f*x0*(1.0f + erff(x0*gc));
        x1 = 0.5f*x1*(1.0f + erff(x1*gc));
        *(float2*)(mid + (size_t)m*HH + col) = make_float2(x0, x1);
    }
}

// ---------------- W2 GEMM (K=512) + residual -> out : grid (2, 128), 128 thr ----------------
__global__ void __launch_bounds__(128)
w2_kernel(const float* __restrict__ mid, const float* __restrict__ W2,
          const float* __restrict__ b2, const float* __restrict__ y,
          float* __restrict__ out) {
    __shared__ SmemG64 sg;
    const int bn = blockIdx.x << 6, bm = blockIdx.y << 3;
    ull acc[8];
    gemm64<HH>(sg, mid, HH, bm, W2, CC, bn, acc);
    ull s0, s1;
    gemm64_red(sg, acc, s0, s1);
    const int r0 = threadIdx.x >> 5, cl = threadIdx.x & 31;
    const int col = bn + (cl << 1);
    float2 bias = *(const float2*)(b2 + col);
    #pragma unroll
    for (int i = 0; i < 2; i++) {
        int m = bm + r0 + i*4;
        float x0, x1; unpack2(i ? s1 : s0, x0, x1);
        float2 yv = *(const float2*)(y + (size_t)m*CC + col);
        *(float2*)(out + (size_t)m*CC + col) = make_float2(x0 + bias.x + yv.x, x1 + bias.y + yv.y);
    }
}

// ---------------- launch ----------------
extern "C" void kernel_launch(void* const* d_in, const int* in_sizes, int n_in,
                              void* d_out, int out_size) {
    const float* x       = (const float*)d_in[0];
    const float* ln1_g   = (const float*)d_in[1];
    const float* ln1_b   = (const float*)d_in[2];
    const float* mu      = (const float*)d_in[3];
    const float* Wr      = (const float*)d_in[4];
    const float* br      = (const float*)d_in[5];
    const float* Wk      = (const float*)d_in[6];
    const float* bk      = (const float*)d_in[7];
    const float* Wv      = (const float*)d_in[8];
    const float* bv      = (const float*)d_in[9];
    const float* w_decay = (const float*)d_in[10];
    const float* Wo      = (const float*)d_in[11];
    const float* bo      = (const float*)d_in[12];
    const float* ln2_g   = (const float*)d_in[13];
    const float* ln2_b   = (const float*)d_in[14];
    const float* W1      = (const float*)d_in[15];
    const float* b1      = (const float*)d_in[16];
    const float* W2      = (const float*)d_in[17];
    const float* b2      = (const float*)d_in[18];
    float* out = (float*)d_out;

    float *hs, *r_, *k_, *v_, *wkp, *y, *h2, *mid;
    cudaGetSymbolAddress((void**)&hs,  g_hs);
    cudaGetSymbolAddress((void**)&r_,  g_r);
    cudaGetSymbolAddress((void**)&k_,  g_k);
    cudaGetSymbolAddress((void**)&v_,  g_v);
    cudaGetSymbolAddress((void**)&wkp, g_wk);
    cudaGetSymbolAddress((void**)&y,   g_y);
    cudaGetSymbolAddress((void**)&h2,  g_h2);
    cudaGetSymbolAddress((void**)&mid, g_mid);

    ln_shift_kernel<<<128, 256>>>(x, ln1_g, ln1_b, mu, hs);
    rkv_kernel<<<dim3(2, 128, 3), 128>>>(hs, Wr, br, Wk, bk, Wv, bv, r_, k_, v_);
    wkv_kernel<<<128, 1024>>>(k_, v_, r_, w_decay, wkp);
    wo_ln_kernel<<<128, 128>>>(wkp, Wo, bo, x, ln2_g, ln2_b, y, h2);
    w1_kernel<<<dim3(8, 128), 128>>>(h2, W1, b1, mid);
    w2_kernel<<<dim3(2, 128), 128>>>(mid, W2, b2, y, out);
}